// round 9
// baseline (speedup 1.0000x reference)
#include <cuda_runtime.h>
#include <cstdint>

// ROI bilinear pooling (TF1 resize_images, align_corners=False).
// img:  (1024,1024,128) fp32 (pixel = 512B). rois: (512,4) = (x1,y1,w,h),
// x1,y1 in [0,768), w,h in [16,256). out: (512,7,7,128) fp32.
//
// Geometry (proved): no reference clamp ever fires; the 4 taps are pixels
// (y,y+1) x (x,x+1) = two contiguous 1024B row segments.
//
// Strategy: persistent warps + DEEP cp.async (LDGSTS) pipeline.
// Every prior variant (LDG / TMA-per-warp) holds only ~2KB in flight per
// warp -> ~8KB/SM outstanding -> DRAM pinned at ~46% active (Little's law
// needs ~16KB/SM at 8TB/s x ~300ns). cp.async has no depth cap and no
// register cost for in-flight data: 4 tiles x 2KB in flight per warp,
// 16 warps/SM -> far above the required outstanding bytes.
//
// Grid 296 blocks x 256 thr (2368 warps, 2 blocks/SM); each warp runs
// ~10.6 tiles of the 25088 total with a 4-stage pipeline:
//   issue(cp.async x4 per lane, commit) ... wait_group(3) -> blend -> store.

#define POOL 7
#define IMG_W 1024
#define PIX_BYTES 512
#define TILES_TOTAL (512 * POOL * POOL)    // 25088
#define WARPS_PER_BLOCK 8
#define NUM_BLOCKS 296
#define TOTAL_WARPS (NUM_BLOCKS * WARPS_PER_BLOCK)  // 2368
#define STAGES 4
#define TILE_BYTES 2048
#define SMEM_TOTAL (WARPS_PER_BLOCK * STAGES * TILE_BYTES)  // 64KB

__device__ __forceinline__ uint32_t smem_u32(const void* p) {
    uint32_t a;
    asm("{ .reg .u64 t; cvta.to.shared.u64 t, %1; cvt.u32.u64 %0, t; }"
        : "=r"(a) : "l"(p));
    return a;
}

__device__ __forceinline__ void cp16(uint32_t dst, const char* src) {
    asm volatile("cp.async.cg.shared.global [%0], [%1], 16;"
                 :: "r"(dst), "l"(src) : "memory");
}

__global__ __launch_bounds__(32 * WARPS_PER_BLOCK) void roi_pool_kernel(
    const char* __restrict__ img,
    const float4* __restrict__ rois,
    float4* __restrict__ out)
{
    extern __shared__ char smem[];
    const uint32_t smem_base = smem_u32(smem);

    const int tid  = threadIdx.x;
    const int wid  = tid >> 5;
    const int lane = tid & 31;
    const int gwarp = blockIdx.x * WARPS_PER_BLOCK + wid;

    const uint32_t wbuf = smem_base + wid * (STAGES * TILE_BYTES);

    // per-stage metadata kept in registers
    float sfx[STAGES], sfy[STAGES];
    int   stile[STAGES];

    // ---- issue one tile's loads into stage s (uniform warp control flow) ----
    auto issue = [&](int t, int s) {
        stile[s] = t;
        if (t >= TILES_TOTAL) { sfx[s] = 0.f; sfy[s] = 0.f; return; }
        const int roi = t / (POOL * POOL);
        const int pos = t - roi * (POOL * POOL);
        const int oy  = pos / POOL;
        const int ox  = pos - oy * POOL;

        const float4 r = __ldg(&rois[roi]);   // 8KB table, L1-hot
        const int x1 = (int)r.x, y1 = (int)r.y;
        const int w  = (int)r.z, h  = (int)r.w;

        const float srcy = (float)oy * ((float)h / (float)POOL);
        const int   ly   = (int)floorf(srcy);
        sfy[s] = srcy - (float)ly;
        const int y_lo = y1 + ly;

        const float srcx = (float)ox * ((float)w / (float)POOL);
        const int   lx   = (int)floorf(srcx);
        sfx[s] = srcx - (float)lx;
        const int x_lo = x1 + lx;

        const char* src0 = img + ((size_t)y_lo * IMG_W + x_lo) * PIX_BYTES;
        const char* src1 = src0 + (size_t)IMG_W * PIX_BYTES;
        const uint32_t buf = wbuf + s * TILE_BYTES;

        // each lane copies 32B of each 1024B segment (2 x 16B)
        const int o = lane * 32;
        cp16(buf + o,              src0 + o);
        cp16(buf + o + 16,         src0 + o + 16);
        cp16(buf + 1024 + o,       src1 + o);
        cp16(buf + 1024 + o + 16,  src1 + o + 16);
    };

    // ---- prologue: fill all stages ----
    int t_issue = gwarp;
    #pragma unroll
    for (int s = 0; s < STAGES; s++) {
        issue(t_issue, s);
        asm volatile("cp.async.commit_group;" ::: "memory");
        t_issue += TOTAL_WARPS;
    }

    // ---- steady loop ----
    const int iters = (TILES_TOTAL - gwarp + TOTAL_WARPS - 1) / TOTAL_WARPS;
    int s = 0;
    for (int i = 0; i < iters; i++) {
        asm volatile("cp.async.wait_group %0;" :: "n"(STAGES - 1) : "memory");
        __syncwarp();

        const int t = stile[s];
        const float fx = sfx[s];
        const float fy = sfy[s];
        const uint32_t buf = wbuf + s * TILE_BYTES;

        float4 v00, v01, v10, v11;
        const uint32_t off = lane * 16;
        asm volatile("ld.shared.v4.f32 {%0,%1,%2,%3}, [%4];"
                     : "=f"(v00.x), "=f"(v00.y), "=f"(v00.z), "=f"(v00.w)
                     : "r"(buf + off));
        asm volatile("ld.shared.v4.f32 {%0,%1,%2,%3}, [%4];"
                     : "=f"(v01.x), "=f"(v01.y), "=f"(v01.z), "=f"(v01.w)
                     : "r"(buf + 512u + off));
        asm volatile("ld.shared.v4.f32 {%0,%1,%2,%3}, [%4];"
                     : "=f"(v10.x), "=f"(v10.y), "=f"(v10.z), "=f"(v10.w)
                     : "r"(buf + 1024u + off));
        asm volatile("ld.shared.v4.f32 {%0,%1,%2,%3}, [%4];"
                     : "=f"(v11.x), "=f"(v11.y), "=f"(v11.z), "=f"(v11.w)
                     : "r"(buf + 1536u + off));

        const float gx = 1.0f - fx;
        const float gy = 1.0f - fy;
        const float w00 = gy * gx, w01 = gy * fx, w10 = fy * gx, w11 = fy * fx;

        float4 o;
        o.x = v00.x * w00 + v01.x * w01 + v10.x * w10 + v11.x * w11;
        o.y = v00.y * w00 + v01.y * w01 + v10.y * w10 + v11.y * w11;
        o.z = v00.z * w00 + v01.z * w01 + v10.z * w10 + v11.z * w11;
        o.w = v00.w * w00 + v01.w * w01 + v10.w * w10 + v11.w * w11;

        out[(size_t)t * 32 + lane] = o;

        __syncwarp();  // all lanes done reading stage s before refilling it
        issue(t_issue, s);
        asm volatile("cp.async.commit_group;" ::: "memory");
        t_issue += TOTAL_WARPS;

        s = (s + 1) & (STAGES - 1);
    }
}

extern "C" void kernel_launch(void* const* d_in, const int* in_sizes, int n_in,
                              void* d_out, int out_size)
{
    const char*   img  = (const char*)d_in[0];     // (1,1024,1024,128) fp32
    const float4* rois = (const float4*)d_in[1];   // (1,512,4) fp32
    float4* out = (float4*)d_out;                  // (1,512,7,7,128) fp32

    cudaFuncSetAttribute(roi_pool_kernel,
                         cudaFuncAttributeMaxDynamicSharedMemorySize, SMEM_TOTAL);
    dim3 block(32 * WARPS_PER_BLOCK);   // 256 threads
    dim3 grid(NUM_BLOCKS);              // 296 = 2 per SM
    roi_pool_kernel<<<grid, block, SMEM_TOTAL>>>(img, rois, out);
}

// round 11
// speedup vs baseline: 1.3031x; 1.3031x over previous
#include <cuda_runtime.h>
#include <cstdint>

// ROI bilinear pooling (TF1 resize_images, align_corners=False).
// img:  (1024, 1024, 128) fp32, channels contiguous (pixel = 512B).
// rois: (512, 4) fp32 -> (x1, y1, w, h); x1,y1 in [0,768), w,h in [16,256).
// out:  (512, 7, 7, 128) fp32.
//
// Best-performing structure (R1): one warp per (roi, oy, ox) tile,
// 32 lanes x float4 = 128 channels, 4 coalesced 512B gathers.
// This round: 512-thread blocks (16 warps, exactly 2048 thr/SM at 32 regs)
// and linear warp indexing to cut block-churn occupancy loss.
// Geometry (proved from input ranges): no reference clamp ever fires,
// hi = lo + 1 always.

#define POOL 7
#define IMG_W 1024
#define IMG_H 1024
#define C4 32                              // 128 channels / 4 floats
#define WARPS_PER_BLOCK 16
#define TOTAL_WARPS (512 * POOL * POOL)    // 25088
#define NUM_BLOCKS (TOTAL_WARPS / WARPS_PER_BLOCK)  // 1568

__global__ __launch_bounds__(32 * WARPS_PER_BLOCK, 4) void roi_pool_kernel(
    const float4* __restrict__ img,   // [1024][1024][32] float4
    const float4* __restrict__ rois,  // [512] float4 (x1,y1,w,h)
    float4* __restrict__ out)         // [512*49][32] float4
{
    const int tid  = threadIdx.x;
    const int lane = tid & 31;
    const int warp = blockIdx.x * WARPS_PER_BLOCK + (tid >> 5);

    const int roi = warp / (POOL * POOL);
    const int pos = warp - roi * (POOL * POOL);
    const int oy  = pos / POOL;
    const int ox  = pos - oy * POOL;

    const float4 r = __ldg(&rois[roi]);
    const int x1 = (int)r.x;
    const int y1 = (int)r.y;
    const int w  = (int)r.z;
    const int h  = (int)r.w;

    // y axis (exact fp32 ops of the reference; interior => clamps are no-ops)
    const float srcy = (float)oy * ((float)h / (float)POOL);
    const int   ly   = (int)floorf(srcy);
    const float fy   = srcy - (float)ly;
    const int   y_lo = y1 + ly;          // y_hi = y_lo + 1 (proved in-range)

    // x axis
    const float srcx = (float)ox * ((float)w / (float)POOL);
    const int   lx   = (int)floorf(srcx);
    const float fx   = srcx - (float)lx;
    const int   x_lo = x1 + lx;          // x_hi = x_lo + 1

    // 4 coalesced 512B gathers (LDG.E.128 per lane), front-batched
    const uint32_t base = ((uint32_t)y_lo * IMG_W + (uint32_t)x_lo) * C4 + lane;
    const float4 v00 = __ldg(&img[base]);
    const float4 v01 = __ldg(&img[base + C4]);
    const float4 v10 = __ldg(&img[base + IMG_W * C4]);
    const float4 v11 = __ldg(&img[base + IMG_W * C4 + C4]);

    const float gx = 1.0f - fx;
    const float gy = 1.0f - fy;
    const float w00 = gy * gx;
    const float w01 = gy * fx;
    const float w10 = fy * gx;
    const float w11 = fy * fx;

    float4 o;
    o.x = v00.x * w00 + v01.x * w01 + v10.x * w10 + v11.x * w11;
    o.y = v00.y * w00 + v01.y * w01 + v10.y * w10 + v11.y * w11;
    o.z = v00.z * w00 + v01.z * w01 + v10.z * w10 + v11.z * w11;
    o.w = v00.w * w00 + v01.w * w01 + v10.w * w10 + v11.w * w11;

    out[(size_t)warp * C4 + lane] = o;
}

extern "C" void kernel_launch(void* const* d_in, const int* in_sizes, int n_in,
                              void* d_out, int out_size)
{
    const float4* img  = (const float4*)d_in[0];   // (1,1024,1024,128) fp32
    const float4* rois = (const float4*)d_in[1];   // (1,512,4) fp32
    float4* out = (float4*)d_out;                  // (1,512,7,7,128) fp32

    dim3 block(32 * WARPS_PER_BLOCK);   // 512 threads, 16 warps
    dim3 grid(NUM_BLOCKS);              // 1568 blocks
    roi_pool_kernel<<<grid, block>>>(img, rois, out);
}

// round 12
// speedup vs baseline: 1.3072x; 1.0031x over previous
#include <cuda_runtime.h>
#include <cstdint>

// ROI bilinear pooling (TF1 resize_images, align_corners=False).
// img:  (1024, 1024, 128) fp32, channels contiguous (pixel = 512B).
// rois: (512, 4) fp32 -> (x1, y1, w, h); x1,y1 in [0,768), w,h in [16,256).
// out:  (512, 7, 7, 128) fp32.
//
// Champion structure (R1, 10.18us): one warp per (roi, oy, ox) tile,
// 32 lanes x float4 = 128 channels, 4 coalesced 512B gathers
// (two contiguous 1KB row segments). Block (32,7), grid (7,512).
//
// Measured across 6 structurally different designs (LDG / TMA / cp.async,
// 8KB..96KB per-SM in flight): all plateau at ~3.8TB/s -> DRAM random-
// granule efficiency floor. Traffic is compulsory (no inter-tile reuse),
// so this round only trims: ld.global.cg for zero-reuse image lines,
// clamp-free uint32 index math (clamps proved no-ops from input ranges).

#define POOL 7
#define IMG_W 1024
#define C4 32  // 128 channels / 4 floats

__device__ __forceinline__ float4 ldg_cg(const float4* p) {
    float4 v;
    asm("ld.global.cg.v4.f32 {%0,%1,%2,%3}, [%4];"
        : "=f"(v.x), "=f"(v.y), "=f"(v.z), "=f"(v.w)
        : "l"(p));
    return v;
}

__global__ __launch_bounds__(32 * POOL) void roi_pool_kernel(
    const float4* __restrict__ img,   // [1024][1024][32] float4
    const float4* __restrict__ rois,  // [512] float4 (x1,y1,w,h)
    float4* __restrict__ out)         // [512][7][7][32] float4
{
    const int roi  = blockIdx.y;
    const int oy   = blockIdx.x;      // 0..6
    const int ox   = threadIdx.y;     // 0..6
    const int lane = threadIdx.x;     // 0..31 (float4 groups)

    const float4 r = __ldg(&rois[roi]);
    const int x1 = (int)r.x;
    const int y1 = (int)r.y;
    const int w  = (int)r.z;
    const int h  = (int)r.w;

    // y axis (exact fp32 ops of the reference; interior => clamps are no-ops:
    // for h>=16, ly <= floor(6h/7) <= h-2 so hy = ly+1, and y1+hy < 1024)
    const float srcy = (float)oy * ((float)h / (float)POOL);
    const int   ly   = (int)floorf(srcy);
    const float fy   = srcy - (float)ly;
    const int   y_lo = y1 + ly;          // y_hi = y_lo + 1

    // x axis
    const float srcx = (float)ox * ((float)w / (float)POOL);
    const int   lx   = (int)floorf(srcx);
    const float fx   = srcx - (float)lx;
    const int   x_lo = x1 + lx;          // x_hi = x_lo + 1

    // 4 coalesced 512B gathers = two contiguous 1KB segments
    const uint32_t base = ((uint32_t)y_lo * IMG_W + (uint32_t)x_lo) * C4 + lane;
    const float4 v00 = ldg_cg(&img[base]);
    const float4 v01 = ldg_cg(&img[base + C4]);
    const float4 v10 = ldg_cg(&img[base + IMG_W * C4]);
    const float4 v11 = ldg_cg(&img[base + IMG_W * C4 + C4]);

    const float gx = 1.0f - fx;
    const float gy = 1.0f - fy;
    const float w00 = gy * gx;
    const float w01 = gy * fx;
    const float w10 = fy * gx;
    const float w11 = fy * fx;

    float4 o;
    o.x = v00.x * w00 + v01.x * w01 + v10.x * w10 + v11.x * w11;
    o.y = v00.y * w00 + v01.y * w01 + v10.y * w10 + v11.y * w11;
    o.z = v00.z * w00 + v01.z * w01 + v10.z * w10 + v11.z * w11;
    o.w = v00.w * w00 + v01.w * w01 + v10.w * w10 + v11.w * w11;

    out[(((size_t)roi * POOL + oy) * POOL + ox) * C4 + lane] = o;
}

extern "C" void kernel_launch(void* const* d_in, const int* in_sizes, int n_in,
                              void* d_out, int out_size)
{
    const float4* img  = (const float4*)d_in[0];   // (1,1024,1024,128) fp32
    const float4* rois = (const float4*)d_in[1];   // (1,512,4) fp32
    float4* out = (float4*)d_out;                  // (1,512,7,7,128) fp32

    dim3 block(32, POOL);        // 224 threads: 7 warps, one per ox
    dim3 grid(POOL, 512);        // (oy, roi)
    roi_pool_kernel<<<grid, block>>>(img, rois, out);
}

// round 13
// speedup vs baseline: 1.4580x; 1.1154x over previous
#include <cuda_runtime.h>
#include <cstdint>

// ROI bilinear pooling (TF1 resize_images, align_corners=False).
// img:  (1024, 1024, 128) fp32, channels contiguous (pixel = 512B).
// rois: (512, 4) fp32 -> (x1, y1, w, h); x1,y1 in [0,768), w,h in [16,256).
// out:  (512, 7, 7, 128) fp32.
//
// FINAL (champion) kernel. One warp per (roi, oy, ox) tile: 32 lanes x
// float4 = 128 channels, 4 coalesced 512B gathers forming two contiguous
// 1KB row segments. Block (32,7) = 7 warps (one per ox), grid (7,512).
//
// Optimization record: 7 designs measured (warp-LDG, 2x-MLP LDG,
// evict_last LDG, per-warp TMA bulk, deep cp.async pipeline, 512-thr LDG,
// .cg LDG). All plateau at 3.75-3.94 TB/s flushed DRAM with no SM-side
// pipe saturated => memory-side floor: random ~1KB granule reads over a
// 512MB footprint run at ~48% DRAM streaming efficiency, and the traffic
// is compulsory (w,h>=16 => zero tap reuse between output positions).
// Clamps from the reference are proved no-ops (lx <= 6w/7 <= w-2 for
// w>=16 => hx=lx+1; x1+hx <= 986 < 1024; same for y), removed.

#define POOL 7
#define IMG_W 1024
#define C4 32  // 128 channels / 4 floats

__global__ __launch_bounds__(32 * POOL) void roi_pool_kernel(
    const float4* __restrict__ img,   // [1024][1024][32] float4
    const float4* __restrict__ rois,  // [512] float4 (x1,y1,w,h)
    float4* __restrict__ out)         // [512][7][7][32] float4
{
    const int roi  = blockIdx.y;
    const int oy   = blockIdx.x;      // 0..6
    const int ox   = threadIdx.y;     // 0..6
    const int lane = threadIdx.x;     // 0..31 (float4 groups)

    const float4 r = __ldg(&rois[roi]);
    const int x1 = (int)r.x;
    const int y1 = (int)r.y;
    const int w  = (int)r.z;
    const int h  = (int)r.w;

    // y axis (exact fp32 ops of the reference; interior => clamps no-ops)
    const float srcy = (float)oy * ((float)h / (float)POOL);
    const int   ly   = (int)floorf(srcy);
    const float fy   = srcy - (float)ly;
    const int   y_lo = y1 + ly;          // y_hi = y_lo + 1

    // x axis
    const float srcx = (float)ox * ((float)w / (float)POOL);
    const int   lx   = (int)floorf(srcx);
    const float fx   = srcx - (float)lx;
    const int   x_lo = x1 + lx;          // x_hi = x_lo + 1

    // 4 coalesced 512B gathers = two contiguous 1KB segments
    const uint32_t base = ((uint32_t)y_lo * IMG_W + (uint32_t)x_lo) * C4 + lane;
    const float4 v00 = __ldg(&img[base]);
    const float4 v01 = __ldg(&img[base + C4]);
    const float4 v10 = __ldg(&img[base + IMG_W * C4]);
    const float4 v11 = __ldg(&img[base + IMG_W * C4 + C4]);

    const float gx = 1.0f - fx;
    const float gy = 1.0f - fy;
    const float w00 = gy * gx;
    const float w01 = gy * fx;
    const float w10 = fy * gx;
    const float w11 = fy * fx;

    float4 o;
    o.x = v00.x * w00 + v01.x * w01 + v10.x * w10 + v11.x * w11;
    o.y = v00.y * w00 + v01.y * w01 + v10.y * w10 + v11.y * w11;
    o.z = v00.z * w00 + v01.z * w01 + v10.z * w10 + v11.z * w11;
    o.w = v00.w * w00 + v01.w * w01 + v10.w * w10 + v11.w * w11;

    out[(((size_t)roi * POOL + oy) * POOL + ox) * C4 + lane] = o;
}

extern "C" void kernel_launch(void* const* d_in, const int* in_sizes, int n_in,
                              void* d_out, int out_size)
{
    const float4* img  = (const float4*)d_in[0];   // (1,1024,1024,128) fp32
    const float4* rois = (const float4*)d_in[1];   // (1,512,4) fp32
    float4* out = (float4*)d_out;                  // (1,512,7,7,128) fp32

    dim3 block(32, POOL);        // 224 threads: 7 warps, one per ox
    dim3 grid(POOL, 512);        // (oy, roi)
    roi_pool_kernel<<<grid, block>>>(img, rois, out);
}